// round 5
// baseline (speedup 1.0000x reference)
#include <cuda_runtime.h>
#include <cuda_bf16.h>
#include <cstdint>

typedef unsigned int u32;
typedef unsigned long long u64t;

// ===================== prep: hi/lo bf16 split of W1 ========================
// sets: 0=e_hi 1=e_lo 2=s_hi 3=s_lo ; each [96][768]
__device__ __align__(16) __nv_bfloat16 g_prep[4 * 96 * 768];

__global__ void prep_w1(const float* __restrict__ eW1, const float* __restrict__ sW1)
{
    int idx = blockIdx.x * 256 + threadIdx.x;      // 0 .. 147455
    if (idx >= 2 * 73728) return;
    int br = idx / 73728;                          // 0=e, 1=s
    int r  = idx - br * 73728;
    float x = (br ? sW1 : eW1)[r];
    __nv_bfloat16 hi = __float2bfloat16(x);
    __nv_bfloat16 lo = __float2bfloat16(x - __bfloat162float(hi));
    g_prep[(br * 2 + 0) * 73728 + r] = hi;
    g_prep[(br * 2 + 1) * 73728 + r] = lo;
}

// ===================== helpers =============================================
__device__ __forceinline__ u64t fma2(u64t a, u64t b, u64t c) {
    u64t d;
    asm("fma.rn.f32x2 %0, %1, %2, %3;" : "=l"(d) : "l"(a), "l"(b), "l"(c));
    return d;
}
__device__ __forceinline__ float red2(u64t v) {
    return __uint_as_float((u32)v) + __uint_as_float((u32)(v >> 32));
}
__device__ __forceinline__ u64t pack2(float lo, float hi) {
    return (u64t)__float_as_uint(lo) | ((u64t)__float_as_uint(hi) << 32);
}
__device__ __forceinline__ void split4(float4 q, u64t& hv, u64t& lv) {
    __nv_bfloat162 h01 = __floats2bfloat162_rn(q.x, q.y);
    __nv_bfloat162 h23 = __floats2bfloat162_rn(q.z, q.w);
    float2 f01 = __bfloat1622float2(h01);
    float2 f23 = __bfloat1622float2(h23);
    __nv_bfloat162 l01 = __floats2bfloat162_rn(q.x - f01.x, q.y - f01.y);
    __nv_bfloat162 l23 = __floats2bfloat162_rn(q.z - f23.x, q.w - f23.y);
    hv = (u64t)(*(u32*)&h01) | ((u64t)(*(u32*)&h23) << 32);
    lv = (u64t)(*(u32*)&l01) | ((u64t)(*(u32*)&l23) << 32);
}
// m16n8k16 row.col bf16 -> f32
__device__ __forceinline__ void mma_bf16(float c[4], u32 a0, u32 a1, u32 a2, u32 a3,
                                         u32 b0, u32 b1) {
    asm volatile("mma.sync.aligned.m16n8k16.row.col.f32.bf16.bf16.f32 "
        "{%0,%1,%2,%3}, {%4,%5,%6,%7}, {%8,%9}, {%0,%1,%2,%3};"
        : "+f"(c[0]), "+f"(c[1]), "+f"(c[2]), "+f"(c[3])
        : "r"(a0), "r"(a1), "r"(a2), "r"(a3), "r"(b0), "r"(b1));
}

// ===================== smem layout (bytes) =================================
// mainloop:
#define SM_AH 0            // 256 rows * 80 B          = 20480
#define SM_AL 20480        //                            20480
#define SM_B  40960        // 4 sets * 96 rows * 80 B  = 30720 -> end 71680
// tail (y1 region overlays mainloop A/B):
#define TY1   0            // 256 rows * 98 f * 4       = 100352
#define TW    100352       // weight region, 12516 floats = 50064 -> end 150416
#define TY2   150592       // 256 rows * 50 f * 4       =  51200 -> end 201792
#define SMEM_BYTES 201792
// float offsets within weight region:
#define OW2E 0
#define OW2S 4608
#define OW3E 9216
#define OW3S 10368
#define OW4E 11520
#define OW4S 11808
#define OW5  12096
#define OE5  12120
#define OSE  12132
#define OT0  12260
#define OT1  12388

__global__ __launch_bounds__(512, 1) void fused_mma(
    const float* __restrict__ in,
    const float* __restrict__ sW2, const float* __restrict__ sW3,
    const float* __restrict__ sW4, const float* __restrict__ sW5,
    const float* __restrict__ eW2, const float* __restrict__ eW3,
    const float* __restrict__ eW4, const float* __restrict__ eW5,
    const float* __restrict__ s_seq, const float* __restrict__ s_pair,
    const float* __restrict__ e_seq, const float* __restrict__ e_pair,
    const float* __restrict__ cross_w,
    float* __restrict__ out)
{
    extern __shared__ __align__(1024) char sm[];
    float* y1 = (float*)(sm + TY1);
    float* wf = (float*)(sm + TW);
    float* y2 = (float*)(sm + TY2);

    const int tid = threadIdx.x;
    const int r0g = blockIdx.x * 64;

    const float ep0 = e_pair[0], ep1 = e_pair[1];
    const float sp0 = s_pair[0], sp1 = s_pair[1];
    const float es0 = e_seq[0], es1 = e_seq[1], es2 = e_seq[2], es3 = e_seq[3];
    const float ss0 = s_seq[0], ss1 = s_seq[1], ss2 = s_seq[2], ss3 = s_seq[3];

    // ---- load tail weights early (region disjoint from mainloop smem) ----
    for (int i = tid; i < 4608; i += 512) { wf[OW2E + i] = eW2[i]; wf[OW2S + i] = sW2[i]; }
    for (int i = tid; i < 1152; i += 512) { wf[OW3E + i] = eW3[i]; wf[OW3S + i] = sW3[i]; }
    if (tid < 288) { wf[OW4E + tid] = eW4[tid]; wf[OW4S + tid] = sW4[tid]; }
    if (tid >= 288 && tid < 312) wf[OW5 + tid - 288] = sW5[tid - 288];
    if (tid >= 320 && tid < 332) {
        int k = tid - 320; float s = 0.f;
#pragma unroll
        for (int h = 0; h < 8; h++) s += eW5[h * 12 + k];
        wf[OE5 + k] = s;
    }

    // ===================== mainloop: layer 1 on mma.sync ===================
    const int w    = tid >> 5;          // warp 0..15
    const int lane = tid & 31;
    const int b    = w >> 3;            // 0=e, 1=s
    const int wm   = w & 7;             // m16 block within tile
    const int fr   = lane >> 2;         // fragment row 0..7
    const int qk   = (lane & 3) * 2;    // fragment k pair

    // staging thread mapping
    const int sr = tid >> 3;            // 0..63 batch row
    const int sk = tid & 7;             // 0..7 float4 group within 32-k chunk
    const float* inrow = in + (size_t)(r0g + sr) * 3072 + sk * 4;

    // A-frag base (bytes): row = b*128 + wm*16 + fr, col byte = qk*2
    const u32 aoff = (u32)((b * 128 + wm * 16 + fr) * 80 + qk * 2);
    // B-frag base: set row = fr, col byte = qk*2 ; hi set = b*2, lo = b*2+1
    const u32 bHoff = (u32)(SM_B + (b * 2) * 7680 + fr * 80 + qk * 2);
    const u32 bLoff = bHoff + 7680;

    float acc[12][4];
#pragma unroll
    for (int nf = 0; nf < 12; nf++)
#pragma unroll
        for (int c = 0; c < 4; c++) acc[nf][c] = 0.f;

    float4 st0, st1, st2, st3;
    {
        const float* p = inrow;         // kc = 0
        st0 = *(const float4*)(p);
        st1 = *(const float4*)(p + 768);
        st2 = *(const float4*)(p + 1536);
        st3 = *(const float4*)(p + 2304);
    }

    for (int kc = 0; kc < 24; kc++) {
        // ---- build A chunk from staged regs ----
        {
            float4 q; u64t hv, lv;
            u32 abase = (u32)((sr * 2) * 80 + sk * 8);
            // v0: pair_e  (row = 0*128 + sr*2+0)
            q.x = fmaxf(ep0*st0.x + ep1*st2.x, 0.f); q.y = fmaxf(ep0*st0.y + ep1*st2.y, 0.f);
            q.z = fmaxf(ep0*st0.z + ep1*st2.z, 0.f); q.w = fmaxf(ep0*st0.w + ep1*st2.w, 0.f);
            split4(q, hv, lv);
            *(u64t*)(sm + SM_AH + abase) = hv;  *(u64t*)(sm + SM_AL + abase) = lv;
            // v1: seq_e  (row +80)
            q.x = fmaxf(es0*st0.x + es1*st1.x + es2*st2.x + es3*st3.x, 0.f);
            q.y = fmaxf(es0*st0.y + es1*st1.y + es2*st2.y + es3*st3.y, 0.f);
            q.z = fmaxf(es0*st0.z + es1*st1.z + es2*st2.z + es3*st3.z, 0.f);
            q.w = fmaxf(es0*st0.w + es1*st1.w + es2*st2.w + es3*st3.w, 0.f);
            split4(q, hv, lv);
            *(u64t*)(sm + SM_AH + abase + 80) = hv;  *(u64t*)(sm + SM_AL + abase + 80) = lv;
            // v2: pair_s (row +128*80)
            q.x = fmaxf(sp0*st0.x + sp1*st2.x, 0.f); q.y = fmaxf(sp0*st0.y + sp1*st2.y, 0.f);
            q.z = fmaxf(sp0*st0.z + sp1*st2.z, 0.f); q.w = fmaxf(sp0*st0.w + sp1*st2.w, 0.f);
            split4(q, hv, lv);
            *(u64t*)(sm + SM_AH + abase + 10240) = hv;  *(u64t*)(sm + SM_AL + abase + 10240) = lv;
            // v3: seq_s
            q.x = fmaxf(ss0*st0.x + ss1*st1.x + ss2*st2.x + ss3*st3.x, 0.f);
            q.y = fmaxf(ss0*st0.y + ss1*st1.y + ss2*st2.y + ss3*st3.y, 0.f);
            q.z = fmaxf(ss0*st0.z + ss1*st1.z + ss2*st2.z + ss3*st3.z, 0.f);
            q.w = fmaxf(ss0*st0.w + ss1*st1.w + ss2*st2.w + ss3*st3.w, 0.f);
            split4(q, hv, lv);
            *(u64t*)(sm + SM_AH + abase + 10320) = hv;  *(u64t*)(sm + SM_AL + abase + 10320) = lv;
        }
        // ---- B chunk: 4 sets x 96 rows x 32 k ----
#pragma unroll
        for (int i = 0; i < 6; i++) {
            int idx = tid + i * 512;                  // 0..3071
            int set = idx / 768;
            int rem = idx - set * 768;
            int row = rem >> 3, k4 = rem & 7;
            u64t v = *(const u64t*)(g_prep + (size_t)set * 73728 + row * 768 + kc * 32 + k4 * 4);
            *(u64t*)(sm + SM_B + set * 7680 + row * 80 + k4 * 8) = v;
        }
        __syncthreads();

        // ---- prefetch next chunk input ----
        if (kc < 23) {
            const float* p = inrow + (kc + 1) * 32;
            st0 = *(const float4*)(p);
            st1 = *(const float4*)(p + 768);
            st2 = *(const float4*)(p + 1536);
            st3 = *(const float4*)(p + 2304);
        }

        // ---- mma: 2 k16 steps x 12 nf x 3 passes ----
#pragma unroll
        for (int ks = 0; ks < 2; ks++) {
            const u32 ko = ks * 32;   // byte offset of k16 step
            u32 ah0 = *(const u32*)(sm + SM_AH + aoff + ko);
            u32 ah1 = *(const u32*)(sm + SM_AH + aoff + ko + 640);
            u32 ah2 = *(const u32*)(sm + SM_AH + aoff + ko + 16);
            u32 ah3 = *(const u32*)(sm + SM_AH + aoff + ko + 656);
            u32 al0 = *(const u32*)(sm + SM_AL + aoff + ko);
            u32 al1 = *(const u32*)(sm + SM_AL + aoff + ko + 640);
            u32 al2 = *(const u32*)(sm + SM_AL + aoff + ko + 16);
            u32 al3 = *(const u32*)(sm + SM_AL + aoff + ko + 656);
#pragma unroll
            for (int nf = 0; nf < 12; nf++) {
                u32 bo = bHoff + nf * 640 + ko;
                u32 bh0 = *(const u32*)(sm + bo);
                u32 bh1 = *(const u32*)(sm + bo + 16);
                mma_bf16(acc[nf], ah0, ah1, ah2, ah3, bh0, bh1);
                mma_bf16(acc[nf], al0, al1, al2, al3, bh0, bh1);
                u32 blo = bLoff + nf * 640 + ko;
                u32 bl0 = *(const u32*)(sm + blo);
                u32 bl1 = *(const u32*)(sm + blo + 16);
                mma_bf16(acc[nf], ah0, ah1, ah2, ah3, bl0, bl1);
            }
        }
        __syncthreads();
    }

    // ---- epilogue: relu(y1) -> smem [256 rows][98 f], row m = lv*2 + b ----
    {
        const int lv0 = wm * 16 + fr;
        const int m0 = lv0 * 2 + b;
        const int m1 = (lv0 + 8) * 2 + b;
#pragma unroll
        for (int nf = 0; nf < 12; nf++) {
            int nb = nf * 8 + qk;
            *(u64t*)(y1 + m0 * 98 + nb) = pack2(fmaxf(acc[nf][0], 0.f), fmaxf(acc[nf][1], 0.f));
            *(u64t*)(y1 + m1 * 98 + nb) = pack2(fmaxf(acc[nf][2], 0.f), fmaxf(acc[nf][3], 0.f));
        }
    }
    __syncthreads();

    // ===================== tail: layers 2..5 ================================
    const int m = tid >> 1;          // 0..255 vec row
    const int h = tid & 1;           // n-half
    const bool is_e = (m & 1) == 0;
    const int lv = m >> 1;           // r*2 + v

    // ---- layer 2: 96 -> 48 ----
    {
        u64t x[48];
        const u64t* xr = (const u64t*)(y1 + m * 98);
#pragma unroll
        for (int i = 0; i < 48; i++) x[i] = xr[i];
        const float* W = wf + (is_e ? OW2E : OW2S);
#pragma unroll 2
        for (int n = 0; n < 24; n++) {
            const u64t* wr = (const u64t*)(W + (h * 24 + n) * 96);
            u64t s0 = 0, s1 = 0;
#pragma unroll
            for (int kp = 0; kp < 48; kp += 2) {
                s0 = fma2(x[kp], wr[kp], s0);
                s1 = fma2(x[kp + 1], wr[kp + 1], s1);
            }
            y2[m * 50 + h * 24 + n] = fmaxf(red2(s0) + red2(s1), 0.f);
        }
    }
    __syncthreads();

    // ---- layer 3: 48 -> 24 (write into y1 region, stride 26) ----
    {
        u64t x[24];
        const u64t* xr = (const u64t*)(y2 + m * 50);
#pragma unroll
        for (int i = 0; i < 24; i++) x[i] = xr[i];
        const float* W = wf + (is_e ? OW3E : OW3S);
#pragma unroll
        for (int n = 0; n < 12; n++) {
            const u64t* wr = (const u64t*)(W + (h * 12 + n) * 48);
            u64t s0 = 0, s1 = 0;
#pragma unroll
            for (int kp = 0; kp < 24; kp += 2) {
                s0 = fma2(x[kp], wr[kp], s0);
                s1 = fma2(x[kp + 1], wr[kp + 1], s1);
            }
            y1[m * 26 + h * 12 + n] = fmaxf(red2(s0) + red2(s1), 0.f);
        }
    }
    __syncthreads();

    // ---- layer 4 (24 -> 12) + layer-5 dots (h==0 only) ----
    if (h == 0) {
        u64t x[12];
        const u64t* xr = (const u64t*)(y1 + m * 26);
#pragma unroll
        for (int i = 0; i < 12; i++) x[i] = xr[i];
        const float* W = wf + (is_e ? OW4E : OW4S);
        float r4[12];
#pragma unroll
        for (int n = 0; n < 12; n++) {
            const u64t* wr = (const u64t*)(W + n * 24);
            u64t s0 = 0;
#pragma unroll
            for (int kp = 0; kp < 12; kp++) s0 = fma2(x[kp], wr[kp], s0);
            r4[n] = fmaxf(red2(s0), 0.f);      // relu before W5
        }
        if (is_e) {
            float Se = 0.f;
#pragma unroll
            for (int k = 0; k < 12; k++) Se = fmaf(r4[k], wf[OE5 + k], Se);
            wf[OSE + lv] = Se;
        } else {
            float t0 = 0.f, t1 = 0.f;
#pragma unroll
            for (int k = 0; k < 12; k++) {
                t0 = fmaf(r4[k], wf[OW5 + k], t0);
                t1 = fmaf(r4[k], wf[OW5 + 12 + k], t1);
            }
            wf[OT0 + lv] = t0;
            wf[OT1 + lv] = t1;
        }
    }
    __syncthreads();

    // ---- final cross combine ----
    if (tid < 64) {
        const int r = tid;
        const float cw0 = cross_w[0], cw1 = cross_w[1];
        float SeP = wf[OSE + 2 * r], SeS = wf[OSE + 2 * r + 1];
        float o0 = cw0 * SeP * wf[OT0 + 2 * r] + cw1 * SeS * wf[OT0 + 2 * r + 1];
        float o1 = cw0 * SeP * wf[OT1 + 2 * r] + cw1 * SeS * wf[OT1 + 2 * r + 1];
        out[(size_t)(r0g + r) * 2 + 0] = o0;
        out[(size_t)(r0g + r) * 2 + 1] = o1;
    }
}

// ===========================================================================
extern "C" void kernel_launch(void* const* d_in, const int* in_sizes, int n_in,
                              void* d_out, int out_size)
{
    const float* in      = (const float*)d_in[0];
    const float* sW1     = (const float*)d_in[1];
    const float* sW2     = (const float*)d_in[2];
    const float* sW3     = (const float*)d_in[3];
    const float* sW4     = (const float*)d_in[4];
    const float* sW5     = (const float*)d_in[5];
    const float* eW1     = (const float*)d_in[6];
    const float* eW2     = (const float*)d_in[7];
    const float* eW3     = (const float*)d_in[8];
    const float* eW4     = (const float*)d_in[9];
    const float* eW5     = (const float*)d_in[10];
    const float* s_seq   = (const float*)d_in[11];
    const float* s_pair  = (const float*)d_in[12];
    const float* e_seq   = (const float*)d_in[13];
    const float* e_pair  = (const float*)d_in[14];
    const float* cross_w = (const float*)d_in[15];
    float* out = (float*)d_out;

    const int B = in_sizes[0] / 3072;   // 65536

    static int init_done = 0;
    if (!init_done) {
        cudaFuncSetAttribute(fused_mma, cudaFuncAttributeMaxDynamicSharedMemorySize, SMEM_BYTES);
        init_done = 1;
    }
    prep_w1<<<576, 256>>>(eW1, sW1);
    fused_mma<<<B / 64, 512, SMEM_BYTES>>>(
        in, sW2, sW3, sW4, sW5, eW2, eW3, eW4, eW5,
        s_seq, s_pair, e_seq, e_pair, cross_w, out);
}

// round 6
// speedup vs baseline: 2.2648x; 2.2648x over previous
#include <cuda_runtime.h>
#include <cuda_bf16.h>
#include <cstdint>

typedef unsigned int u32;
typedef unsigned long long u64t;

// ============================================================================
// g_prep: packed, fragment-ordered, bank-swizzled hi/lo bf16 split of W1.
// [kc 0..23][br 0..1][n 0..95][ks^(n&1)][q] -> 16B {bh0,bh1,bl0,bl1}
//   bh0 = bf16x2( hi[n][kb+2q], hi[n][kb+2q+1] ),  kb = kc*32 + ks*16
//   bh1 = bf16x2( hi[n][kb+8+2q], hi[n][kb+8+2q+1] ),  bl* same with lo
// ============================================================================
__device__ __align__(16) u32 g_prep[24 * 2 * 96 * 32];   // 589824 B

__device__ __forceinline__ u32 pack_bf16(float a, float b) {
    __nv_bfloat162 h = __floats2bfloat162_rn(a, b);
    return *(u32*)&h;
}

__global__ void prep_w1(const float* __restrict__ eW1, const float* __restrict__ sW1)
{
    int idx = blockIdx.x * 256 + threadIdx.x;        // 0 .. 36863
    if (idx >= 36864) return;
    int q  = idx & 3;
    int ks = (idx >> 2) & 1;
    int n  = (idx >> 3) % 96;
    int t  = (idx >> 3) / 96;
    int kc = t % 24;
    int br = t / 24;
    const float* W = (br ? sW1 : eW1) + (size_t)n * 768 + kc * 32 + ks * 16;
    float x0 = W[2*q], x1 = W[2*q+1], x2 = W[8+2*q], x3 = W[8+2*q+1];
    float h0 = __bfloat162float(__float2bfloat16(x0));
    float h1 = __bfloat162float(__float2bfloat16(x1));
    float h2 = __bfloat162float(__float2bfloat16(x2));
    float h3 = __bfloat162float(__float2bfloat16(x3));
    uint4 v;
    v.x = pack_bf16(x0, x1);
    v.y = pack_bf16(x2, x3);
    v.z = pack_bf16(x0 - h0, x1 - h1);
    v.w = pack_bf16(x2 - h2, x3 - h3);
    u32 off = (u32)kc * 24576 + (u32)br * 12288 + (u32)n * 128
            + (u32)((ks ^ (n & 1)) << 6) + (u32)q * 16;
    *(uint4*)((char*)g_prep + off) = v;
}

// ============================================================================
// helpers
// ============================================================================
__device__ __forceinline__ u32 smem_u32(const void* p) {
    u32 a;
    asm("{ .reg .u64 t; cvta.to.shared.u64 t, %1; cvt.u32.u64 %0, t; }" : "=r"(a) : "l"(p));
    return a;
}
__device__ __forceinline__ u64t fma2(u64t a, u64t b, u64t c) {
    u64t d;
    asm("fma.rn.f32x2 %0, %1, %2, %3;" : "=l"(d) : "l"(a), "l"(b), "l"(c));
    return d;
}
__device__ __forceinline__ float red2(u64t v) {
    return __uint_as_float((u32)v) + __uint_as_float((u32)(v >> 32));
}
__device__ __forceinline__ u64t pack2(float lo, float hi) {
    return (u64t)__float_as_uint(lo) | ((u64t)__float_as_uint(hi) << 32);
}
__device__ __forceinline__ void split4(float4 q, u64t& hv, u64t& lv) {
    __nv_bfloat162 h01 = __floats2bfloat162_rn(q.x, q.y);
    __nv_bfloat162 h23 = __floats2bfloat162_rn(q.z, q.w);
    float2 f01 = __bfloat1622float2(h01);
    float2 f23 = __bfloat1622float2(h23);
    __nv_bfloat162 l01 = __floats2bfloat162_rn(q.x - f01.x, q.y - f01.y);
    __nv_bfloat162 l23 = __floats2bfloat162_rn(q.z - f23.x, q.w - f23.y);
    hv = (u64t)(*(u32*)&h01) | ((u64t)(*(u32*)&h23) << 32);
    lv = (u64t)(*(u32*)&l01) | ((u64t)(*(u32*)&l23) << 32);
}
__device__ __forceinline__ void mma_bf16(float c[4], u32 a0, u32 a1, u32 a2, u32 a3,
                                         u32 b0, u32 b1) {
    asm volatile("mma.sync.aligned.m16n8k16.row.col.f32.bf16.bf16.f32 "
        "{%0,%1,%2,%3}, {%4,%5,%6,%7}, {%8,%9}, {%0,%1,%2,%3};"
        : "+f"(c[0]), "+f"(c[1]), "+f"(c[2]), "+f"(c[3])
        : "r"(a0), "r"(a1), "r"(a2), "r"(a3), "r"(b0), "r"(b1));
}

// ============================================================================
// smem layout (bytes)
//   A stages: stage*40960, hi at +0 (256 rows * 80B), lo at +20480
//   B stages: 81920 + stage*24576   (per stage: br*12288 + n*128 + swz)
//   weights:  131072 (12516 floats)
//   tail y1 overlays [0, 102400): 256 rows * 100 f
// ============================================================================
#define SM_B0   81920
#define B_STAGE 24576
#define SM_W    131072
#define SMEM_BYTES 181248
// weight region float offsets
#define OW2E 0
#define OW2S 4608
#define OW3E 9216
#define OW3S 10368
#define OW4E 11520
#define OW4S 11808
#define OW5  12096
#define OE5  12120
#define OSE  12132
#define OT0  12260
#define OT1  12388

__global__ __launch_bounds__(256, 1) void fused_mma(
    const float* __restrict__ in,
    const float* __restrict__ sW2, const float* __restrict__ sW3,
    const float* __restrict__ sW4, const float* __restrict__ sW5,
    const float* __restrict__ eW2, const float* __restrict__ eW3,
    const float* __restrict__ eW4, const float* __restrict__ eW5,
    const float* __restrict__ s_seq, const float* __restrict__ s_pair,
    const float* __restrict__ e_seq, const float* __restrict__ e_pair,
    const float* __restrict__ cross_w,
    float* __restrict__ out)
{
    extern __shared__ __align__(1024) char sm[];
    float* wf  = (float*)(sm + SM_W);
    float* y1f = (float*)sm;

    const int tid = threadIdx.x;
    const int r0g = blockIdx.x * 64;

    const float ep0 = e_pair[0], ep1 = e_pair[1];
    const float sp0 = s_pair[0], sp1 = s_pair[1];
    const float es0 = e_seq[0], es1 = e_seq[1], es2 = e_seq[2], es3 = e_seq[3];
    const float ss0 = s_seq[0], ss1 = s_seq[1], ss2 = s_seq[2], ss3 = s_seq[3];

    // ---- tail weights (disjoint region) ----
    for (int i = tid; i < 4608; i += 256) { wf[OW2E + i] = eW2[i]; wf[OW2S + i] = sW2[i]; }
    for (int i = tid; i < 1152; i += 256) { wf[OW3E + i] = eW3[i]; wf[OW3S + i] = sW3[i]; }
    if (tid < 144) { wf[OW4E + tid] = eW4[tid]; wf[OW4E + 144 + tid] = eW4[144 + tid];
                     wf[OW4S + tid] = sW4[tid]; wf[OW4S + 144 + tid] = sW4[144 + tid]; }
    if (tid >= 160 && tid < 184) wf[OW5 + tid - 160] = sW5[tid - 160];
    if (tid >= 192 && tid < 204) {
        int k = tid - 192; float s = 0.f;
#pragma unroll
        for (int h = 0; h < 8; h++) s += eW5[h * 12 + k];
        wf[OE5 + k] = s;
    }

    // ---- builder mapping ----
    const int rb = tid >> 3;          // unit0 row 0..31 ; unit1 = rb+32
    const int sk = tid & 7;
    const float* inp0 = in + (size_t)(r0g + rb) * 3072 + sk * 4;
    const float* inp1 = inp0 + (size_t)32 * 3072;

    // ---- mma mapping: warp = m32 x n96 ----
    const int lane = tid & 31;
    const int w    = tid >> 5;
    const int br   = w >> 2;          // 0=e (warps 0-3), 1=s
    const int wm   = w & 3;
    const int fr   = lane >> 2;
    const int ql   = lane & 3;
    const int mb0  = br * 8 + wm * 2;

    u64t gprep;
    asm("cvta.to.global.u64 %0, %1;" : "=l"(gprep) : "l"((const void*)g_prep));
    const u32 b_sm = smem_u32(sm + SM_B0);

    float acc[2][12][4];
#pragma unroll
    for (int im = 0; im < 2; im++)
#pragma unroll
        for (int nf = 0; nf < 12; nf++)
#pragma unroll
            for (int c = 0; c < 4; c++) acc[im][nf][c] = 0.f;

    float4 sA0, sA1, sA2, sA3, sB0, sB1, sB2, sB3;

#define LOAD_STAGE(kcv) { \
    const float* p0 = inp0 + (kcv) * 32; \
    sA0 = *(const float4*)p0; sA1 = *(const float4*)(p0 + 768); \
    sA2 = *(const float4*)(p0 + 1536); sA3 = *(const float4*)(p0 + 2304); \
    const float* p1 = inp1 + (kcv) * 32; \
    sB0 = *(const float4*)p1; sB1 = *(const float4*)(p1 + 768); \
    sB2 = *(const float4*)(p1 + 1536); sB3 = *(const float4*)(p1 + 2304); }

#define BUILD_ONE(stage, roff, t0, t1, t2, t3) { \
    u32 off = (u32)(stage) * 40960 + (roff) * 160 + sk * 8; \
    float4 q; u64t hv, lv; \
    q.x = fmaxf(ep0*t0.x + ep1*t2.x, 0.f); q.y = fmaxf(ep0*t0.y + ep1*t2.y, 0.f); \
    q.z = fmaxf(ep0*t0.z + ep1*t2.z, 0.f); q.w = fmaxf(ep0*t0.w + ep1*t2.w, 0.f); \
    split4(q, hv, lv); \
    *(u64t*)(sm + off) = hv; *(u64t*)(sm + off + 20480) = lv; \
    q.x = fmaxf(es0*t0.x + es1*t1.x + es2*t2.x + es3*t3.x, 0.f); \
    q.y = fmaxf(es0*t0.y + es1*t1.y + es2*t2.y + es3*t3.y, 0.f); \
    q.z = fmaxf(es0*t0.z + es1*t1.z + es2*t2.z + es3*t3.z, 0.f); \
    q.w = fmaxf(es0*t0.w + es1*t1.w + es2*t2.w + es3*t3.w, 0.f); \
    split4(q, hv, lv); \
    *(u64t*)(sm + off + 80) = hv; *(u64t*)(sm + off + 80 + 20480) = lv; \
    q.x = fmaxf(sp0*t0.x + sp1*t2.x, 0.f); q.y = fmaxf(sp0*t0.y + sp1*t2.y, 0.f); \
    q.z = fmaxf(sp0*t0.z + sp1*t2.z, 0.f); q.w = fmaxf(sp0*t0.w + sp1*t2.w, 0.f); \
    split4(q, hv, lv); \
    *(u64t*)(sm + off + 10240) = hv; *(u64t*)(sm + off + 10240 + 20480) = lv; \
    q.x = fmaxf(ss0*t0.x + ss1*t1.x + ss2*t2.x + ss3*t3.x, 0.f); \
    q.y = fmaxf(ss0*t0.y + ss1*t1.y + ss2*t2.y + ss3*t3.y, 0.f); \
    q.z = fmaxf(ss0*t0.z + ss1*t1.z + ss2*t2.z + ss3*t3.z, 0.f); \
    q.w = fmaxf(ss0*t0.w + ss1*t1.w + ss2*t2.w + ss3*t3.w, 0.f); \
    split4(q, hv, lv); \
    *(u64t*)(sm + off + 10320) = hv; *(u64t*)(sm + off + 10320 + 20480) = lv; }

#define BUILD_STAGE(stage) { \
    BUILD_ONE(stage, rb, sA0, sA1, sA2, sA3); \
    BUILD_ONE(stage, rb + 32, sB0, sB1, sB2, sB3); }

#define CPASYNC_B(stage, kcv) { \
    u64t gs = gprep + (u64t)(kcv) * 24576; \
    u32 db = b_sm + (u32)(stage) * B_STAGE; \
    _Pragma("unroll") \
    for (int j = 0; j < 6; j++) { \
        u32 i = (u32)tid * 16 + (u32)j * 4096; \
        asm volatile("cp.async.cg.shared.global [%0], [%1], 16;" \
                     :: "r"(db + i), "l"(gs + i) : "memory"); \
    } \
    asm volatile("cp.async.commit_group;" ::: "memory"); }

    // ---- prologue ----
    LOAD_STAGE(0);
    BUILD_STAGE(0);
    CPASYNC_B(0, 0);
    LOAD_STAGE(1);

    // ---- mainloop ----
    for (int kc = 0; kc < 24; kc++) {
        const int cur = kc & 1, nxt = cur ^ 1;
        asm volatile("cp.async.wait_group 0;" ::: "memory");
        __syncthreads();
        if (kc < 23) { BUILD_STAGE(nxt); CPASYNC_B(nxt, kc + 1); }
        if (kc < 22) { LOAD_STAGE(kc + 2); }

        const u32 a_hi = (u32)cur * 40960 + (u32)(mb0 * 16 + fr) * 80 + (u32)ql * 4;
        const u32 bbase = (u32)(SM_B0 + cur * B_STAGE + br * 12288)
                        + (u32)fr * 128 + (u32)ql * 16;
#pragma unroll
        for (int ks = 0; ks < 2; ks++) {
            u32 ao0 = a_hi + (u32)ks * 32;
            u32 ao1 = ao0 + 1280;     // mb0+1 (16 rows * 80B)
            u32 ah[2][4], al[2][4];
            ah[0][0] = *(const u32*)(sm + ao0);        ah[0][1] = *(const u32*)(sm + ao0 + 640);
            ah[0][2] = *(const u32*)(sm + ao0 + 16);   ah[0][3] = *(const u32*)(sm + ao0 + 656);
            al[0][0] = *(const u32*)(sm + ao0 + 20480); al[0][1] = *(const u32*)(sm + ao0 + 21120);
            al[0][2] = *(const u32*)(sm + ao0 + 20496); al[0][3] = *(const u32*)(sm + ao0 + 21136);
            ah[1][0] = *(const u32*)(sm + ao1);        ah[1][1] = *(const u32*)(sm + ao1 + 640);
            ah[1][2] = *(const u32*)(sm + ao1 + 16);   ah[1][3] = *(const u32*)(sm + ao1 + 656);
            al[1][0] = *(const u32*)(sm + ao1 + 20480); al[1][1] = *(const u32*)(sm + ao1 + 21120);
            al[1][2] = *(const u32*)(sm + ao1 + 20496); al[1][3] = *(const u32*)(sm + ao1 + 21136);
            u32 bsw = bbase + (u32)((ks ^ (fr & 1)) << 6);
#pragma unroll
            for (int nf = 0; nf < 12; nf++) {
                uint4 bv = *(const uint4*)(sm + bsw + nf * 1024);
#pragma unroll
                for (int im = 0; im < 2; im++) {
                    mma_bf16(acc[im][nf], ah[im][0], ah[im][1], ah[im][2], ah[im][3], bv.x, bv.y);
                    mma_bf16(acc[im][nf], al[im][0], al[im][1], al[im][2], al[im][3], bv.x, bv.y);
                    mma_bf16(acc[im][nf], ah[im][0], ah[im][1], ah[im][2], ah[im][3], bv.z, bv.w);
                }
            }
        }
    }
    __syncthreads();   // mainloop smem dead; overlay y1

    // ---- epilogue: relu(y1) -> [256][100] ----
#pragma unroll
    for (int im = 0; im < 2; im++) {
        int m0 = (mb0 + im) * 16 + fr;
        int m1 = m0 + 8;
#pragma unroll
        for (int nf = 0; nf < 12; nf++) {
            int nb = nf * 8 + ql * 2;
            *(u64t*)(y1f + m0 * 100 + nb) = pack2(fmaxf(acc[im][nf][0], 0.f), fmaxf(acc[im][nf][1], 0.f));
            *(u64t*)(y1f + m1 * 100 + nb) = pack2(fmaxf(acc[im][nf][2], 0.f), fmaxf(acc[im][nf][3], 0.f));
        }
    }
    __syncthreads();

    // ---- tail: one vector per thread, all-register chain ----
    {
        const int m = tid;                 // 0..255
        const bool is_e = m < 128;
        const int r = (m & 127) >> 1;
        const int vp = m & 1;

        u64t x[48];
        const u64t* xr = (const u64t*)(y1f + m * 100);
#pragma unroll
        for (int i = 0; i < 48; i++) x[i] = xr[i];

        const float* W2 = wf + (is_e ? OW2E : OW2S);
        float y2r[48];
#pragma unroll 4
        for (int n = 0; n < 48; n++) {
            const u64t* wr = (const u64t*)(W2 + n * 96);
            u64t s0 = 0, s1 = 0;
#pragma unroll
            for (int kp = 0; kp < 48; kp += 2) {
                s0 = fma2(x[kp], wr[kp], s0);
                s1 = fma2(x[kp + 1], wr[kp + 1], s1);
            }
            y2r[n] = fmaxf(red2(s0) + red2(s1), 0.f);
        }
        u64t b2[24];
#pragma unroll
        for (int i = 0; i < 24; i++) b2[i] = pack2(y2r[2*i], y2r[2*i+1]);

        const float* W3 = wf + (is_e ? OW3E : OW3S);
        float y3r[24];
#pragma unroll
        for (int n = 0; n < 24; n++) {
            const u64t* wr = (const u64t*)(W3 + n * 48);
            u64t s0 = 0, s1 = 0;
#pragma unroll
            for (int kp = 0; kp < 24; kp += 2) {
                s0 = fma2(b2[kp], wr[kp], s0);
                s1 = fma2(b2[kp + 1], wr[kp + 1], s1);
            }
            y3r[n] = fmaxf(red2(s0) + red2(s1), 0.f);
        }
        u64t b3[12];
#pragma unroll
        for (int i = 0; i < 12; i++) b3[i] = pack2(y3r[2*i], y3r[2*i+1]);

        const float* W4 = wf + (is_e ? OW4E : OW4S);
        float r4[12];
#pragma unroll
        for (int n = 0; n < 12; n++) {
            const u64t* wr = (const u64t*)(W4 + n * 24);
            u64t s0 = 0;
#pragma unroll
            for (int kp = 0; kp < 12; kp++) s0 = fma2(b3[kp], wr[kp], s0);
            r4[n] = fmaxf(red2(s0), 0.f);       // relu before W5
        }

        const int idx2 = r * 2 + vp;
        if (is_e) {
            float Se = 0.f;
#pragma unroll
            for (int k = 0; k < 12; k++) Se = fmaf(r4[k], wf[OE5 + k], Se);
            wf[OSE + idx2] = Se;
        } else {
            float t0 = 0.f, t1 = 0.f;
#pragma unroll
            for (int k = 0; k < 12; k++) {
                t0 = fmaf(r4[k], wf[OW5 + k], t0);
                t1 = fmaf(r4[k], wf[OW5 + 12 + k], t1);
            }
            wf[OT0 + idx2] = t0;
            wf[OT1 + idx2] = t1;
        }
    }
    __syncthreads();

    if (tid < 64) {
        const int r = tid;
        const float cw0 = cross_w[0], cw1 = cross_w[1];
        float SeP = wf[OSE + 2*r], SeS = wf[OSE + 2*r + 1];
        float o0 = cw0 * SeP * wf[OT0 + 2*r] + cw1 * SeS * wf[OT0 + 2*r + 1];
        float o1 = cw0 * SeP * wf[OT1 + 2*r] + cw1 * SeS * wf[OT1 + 2*r + 1];
        out[(size_t)(r0g + r) * 2 + 0] = o0;
        out[(size_t)(r0g + r) * 2 + 1] = o1;
    }
}

// ============================================================================
extern "C" void kernel_launch(void* const* d_in, const int* in_sizes, int n_in,
                              void* d_out, int out_size)
{
    const float* in      = (const float*)d_in[0];
    const float* sW1     = (const float*)d_in[1];
    const float* sW2     = (const float*)d_in[2];
    const float* sW3     = (const float*)d_in[3];
    const float* sW4     = (const float*)d_in[4];
    const float* sW5     = (const float*)d_in[5];
    const float* eW1     = (const float*)d_in[6];
    const float* eW2     = (const float*)d_in[7];
    const float* eW3     = (const float*)d_in[8];
    const float* eW4     = (const float*)d_in[9];
    const float* eW5     = (const float*)d_in[10];
    const float* s_seq   = (const float*)d_in[11];
    const float* s_pair  = (const float*)d_in[12];
    const float* e_seq   = (const float*)d_in[13];
    const float* e_pair  = (const float*)d_in[14];
    const float* cross_w = (const float*)d_in[15];
    float* out = (float*)d_out;

    const int B = in_sizes[0] / 3072;   // 65536

    static int init_done = 0;
    if (!init_done) {
        cudaFuncSetAttribute(fused_mma, cudaFuncAttributeMaxDynamicSharedMemorySize, SMEM_BYTES);
        init_done = 1;
    }
    prep_w1<<<144, 256>>>(eW1, sW1);
    fused_mma<<<B / 64, 256, SMEM_BYTES>>>(
        in, sW2, sW3, sW4, sW5, eW2, eW3, eW4, eW5,
        s_seq, s_pair, e_seq, e_pair, cross_w, out);
}